// round 4
// baseline (speedup 1.0000x reference)
#include <cuda_runtime.h>
#include <cuda_fp16.h>
#include <cstdint>

#define DEV __device__ __forceinline__

namespace {
constexpr int NPTS = 131072;
constexpr int MT = 64;        // points per CTA
constexpr int THREADS = 256;  // 8 warps: 2(M) x 4(N)
constexpr int KC = 32;        // K chunk
constexpr int AS = 264;       // activation row stride (halves); 528B: 16B-aligned, bank-spread
constexpr int WS = 40;        // weight/feat row stride (halves); 80B: 16B-aligned, bank-spread
constexpr float TWO_PI = 6.2831853071795864769f;

constexpr int CH_H = 256 * WS;   // halves per weight chunk image (10240)
constexpr int CH_B = CH_H * 2;   // 20480 bytes
constexpr int L0_CHUNKS = 17;    // K0 = 544 = 17*32 (515 padded)
constexpr int L0_IMG = L0_CHUNKS * CH_H;
constexpr int SQ_IMG = 8 * CH_H;

// SMEM map (bytes). UNION: {sx,sB,feat-ring} during layer 0, {Wc2,Wn2} later.
constexpr int OFF_ACT   = 0;                    // 64*264*2 = 33792
constexpr int OFF_WRING = 33792;                // 3 * 20480 = 61440
constexpr int OFF_UNION = OFF_WRING + 3 * CH_B; // 95232
constexpr int OFF_SX    = OFF_UNION;            // 1024
constexpr int OFF_SB    = OFF_UNION + 1024;     // 3072
constexpr int OFF_FEAT  = OFF_UNION + 4096;     // 2 * 5120
constexpr int OFF_WC2   = OFF_UNION;            // 3072
constexpr int OFF_WN2   = OFF_UNION + 3072;     // 1024
constexpr int OFF_BIAS  = OFF_FEAT + 2 * 5120;  // 109568
constexpr int OFF_OUTAC = OFF_BIAS + 1024;      // 110592
constexpr int SMEM_BYTES = OFF_OUTAC + 1024;    // 111616 -> 2 CTAs/SM
}

// Weight images in final SMEM layout: L0 17 chunks, then 8 layers x 8 chunks of [256n][40k]
__device__ __half g_Wt[L0_IMG + 8 * SQ_IMG];

// ---------------- helpers ----------------
DEV uint32_t smem_u32(const void* p) {
  uint32_t a;
  asm("{ .reg .u64 t; cvta.to.shared.u64 t, %1; cvt.u32.u64 %0, t; }" : "=r"(a) : "l"(p));
  return a;
}
DEV void cp16(char* s, const char* g) {
  uint32_t sa = smem_u32(s);
  asm volatile("cp.async.ca.shared.global [%0], [%1], 16;" :: "r"(sa), "l"(g));
}
DEV void cp_commit() { asm volatile("cp.async.commit_group;"); }
template <int N> DEV void cp_wait() { asm volatile("cp.async.wait_group %0;" :: "n"(N)); }

DEV void ldsm4(uint32_t* r, uint32_t addr) {
  asm volatile("ldmatrix.sync.aligned.m8n8.x4.shared.b16 {%0,%1,%2,%3}, [%4];"
               : "=r"(r[0]), "=r"(r[1]), "=r"(r[2]), "=r"(r[3]) : "r"(addr));
}
DEV void mma16816(float* d, const uint32_t* a, uint32_t b0, uint32_t b1) {
  asm volatile(
      "mma.sync.aligned.m16n8k16.row.col.f32.f16.f16.f32 "
      "{%0,%1,%2,%3}, {%4,%5,%6,%7}, {%8,%9}, {%0,%1,%2,%3};\n"
      : "+f"(d[0]), "+f"(d[1]), "+f"(d[2]), "+f"(d[3])
      : "r"(a[0]), "r"(a[1]), "r"(a[2]), "r"(a[3]), "r"(b0), "r"(b1));
}
DEV float frelu(float v) { return fmaxf(v, 0.0f); }
DEV uint32_t pack2(float a, float b) {
  __half2 h = __floats2half2_rn(a, b);
  return *reinterpret_cast<uint32_t*>(&h);
}
// Cody-Waite pi reduction + polys; abs err ~4e-6, fast-math safe.
DEV void fsincos(float x, float& s, float& c) {
  float qf = rintf(x * 0.3183098861837907f);
  float r = fmaf(qf, -3.1414794921875f, x);
  r = fmaf(qf, -1.1315941810607910156e-4f, r);
  r = fmaf(qf, -1.9841872589410058936e-9f, r);
  float r2 = r * r;
  float sp = fmaf(r2, 2.7557319e-6f, -1.9841270e-4f);
  sp = fmaf(r2, sp, 8.3333333e-3f);
  sp = fmaf(r2, sp, -1.6666667e-1f);
  s = fmaf(r * r2, sp, r);
  float cp = fmaf(r2, -2.7557319e-7f, 2.4801587e-5f);
  cp = fmaf(r2, cp, -1.3888889e-3f);
  cp = fmaf(r2, cp, 4.1666667e-2f);
  cp = fmaf(r2, cp, -0.5f);
  c = fmaf(r2, cp, 1.0f);
  if (((int)qf) & 1) { s = -s; c = -c; }
}

// ---------------- prep: pack weights into SMEM-image layout ----------------
__global__ void prep_weights(const float* W0, const float* W1, const float* W2,
                             const float* W3, const float* W4, const float* Wc0,
                             const float* Wc1, const float* Wn0, const float* Wn1) {
  int e = blockIdx.x * blockDim.x + threadIdx.x;
  constexpr int TOTAL = L0_IMG + 8 * SQ_IMG;
  if (e >= TOTAL) return;
  int chunk = e / CH_H, r = e % CH_H, n = r / WS, kk = r % WS;
  float v = 0.0f;
  if (kk < KC) {
    if (chunk < L0_CHUNKS) {
      int k = chunk * KC + kk;
      if (k < 515) v = W0[k * 256 + n];
    } else {
      int c2 = chunk - L0_CHUNKS;
      int l = c2 >> 3, k = (c2 & 7) * KC + kk;
      const float* Ws[8] = {W1, W2, W3, W4, Wc0, Wc1, Wn0, Wn1};
      v = Ws[l][k * 256 + n];
    }
  }
  g_Wt[e] = __float2half(v);
}

// ---------------- fused kernel ----------------
struct Params {
  const float *x, *B;
  const float *b0, *b1, *b2, *b3, *b4, *bc0, *bc1, *bc2, *bn0, *bn1, *bn2;
  const float *Wc2, *Wn2;
  const int* t;
  float* out;
};

struct Ctx {
  char* smem;
  uint32_t act32, wring32, feat32;
  int tid, wm, wn, lrow, lk, grp, qp, lane, wid;
};

DEV void prefetch(const Ctx& cx, const __half* gImg, int c, int slot) {
  const char* src = (const char*)(gImg + c * CH_H);
  char* dst = cx.smem + OFF_WRING + slot * CH_B;
#pragma unroll
  for (int i = 0; i < 5; i++) {
    int op = cx.tid + i * THREADS;  // 1280 x 16B
    cp16(dst + op * 16, src + op * 16);
  }
}

DEV void gen_feat(const Ctx& cx, int c, float tot) {
  const float* sx = (const float*)(cx.smem + OFF_SX);
  const float* sB = (const float*)(cx.smem + OFF_SB);
  __half* dst = (__half*)(cx.smem + OFF_FEAT + (c & 1) * 5120);
#pragma unroll
  for (int i = 0; i < 8; i++) {
    int idx = cx.tid + i * THREADS;  // 64*32
    int m = idx >> 5, kk = idx & 31, kg = c * KC + kk;
    float v = 0.0f;
    if (kg < 3) {
      v = sx[m * 4 + kg];
    } else if (kg < 515) {
      int j = (kg < 259) ? (kg - 3) : (kg - 259);
      float px = sx[m * 4] * sB[j];
      px = fmaf(sx[m * 4 + 1], sB[256 + j], px);
      px = fmaf(sx[m * 4 + 2], sB[512 + j], px);
      float sv, cv;
      fsincos(px * TWO_PI, sv, cv);
      float a = fminf(fmaxf(tot - (float)j, 0.0f), 1.0f);
      v = ((kg < 259) ? sv : cv) * a;
    }
    dst[m * WS + kk] = __float2half(v);
  }
}

// MODE 0: act->sAct (in place). MODE 1: dot Wc2 -> outac. MODE 2: dot Wn2 -> outac.
template <int MODE, bool L0F, bool KEEPH>
__device__ __noinline__ void layer(const Ctx& cx, const __half* gImg, int C,
                                   const float* gbias, float tot, uint32_t* hreg,
                                   const Params& p) {
  __half* sAct = (__half*)(cx.smem + OFF_ACT);
  float* sbias = (float*)(cx.smem + OFF_BIAS);
  float* outac = (float*)(cx.smem + OFF_OUTAC);

  float acc[2][8][4];
#pragma unroll
  for (int a = 0; a < 2; a++)
#pragma unroll
    for (int b = 0; b < 8; b++)
#pragma unroll
      for (int d = 0; d < 4; d++) acc[a][b][d] = 0.0f;

  if (L0F) gen_feat(cx, 0, tot);
  prefetch(cx, gImg, 0, 0);
  cp_commit();

  for (int c = 0; c < C; c++) {
    if (c + 1 < C) {
      prefetch(cx, gImg, c + 1, (c + 1) % 3);  // ring-3, distance-1: safe pre-sync
      cp_commit();
      cp_wait<1>();
    } else {
      cp_wait<0>();
    }
    __syncthreads();
    if (c == 0) {
      sbias[cx.tid] = gbias[cx.tid];
      if (MODE != 0) outac[cx.tid] = 0.0f;
    }
    if (L0F && c + 1 < C) gen_feat(cx, c + 1, tot);

    const uint32_t aBase = L0F ? (cx.feat32 + (c & 1) * 5120) : cx.act32;
    const int ast = L0F ? WS : AS;
    const int kb = L0F ? 0 : c * KC;
    const uint32_t wslot = cx.wring32 + (c % 3) * CH_B;

#pragma unroll
    for (int ks = 0; ks < KC; ks += 16) {
      uint32_t a0[4], a1[4];
      uint32_t aA = aBase + ((cx.wm * 32 + cx.lrow) * ast + kb + ks + cx.lk) * 2;
      ldsm4(a0, aA);
      ldsm4(a1, aA + 16 * ast * 2);
      uint32_t bA = wslot + ((cx.wn * 64 + cx.lrow) * WS + ks + cx.lk) * 2;
#pragma unroll
      for (int np = 0; np < 4; np++) {
        uint32_t bb[4];
        ldsm4(bb, bA + np * (16 * WS * 2));
        mma16816(acc[0][2 * np],     a0, bb[0], bb[2]);
        mma16816(acc[0][2 * np + 1], a0, bb[1], bb[3]);
        mma16816(acc[1][2 * np],     a1, bb[0], bb[2]);
        mma16816(acc[1][2 * np + 1], a1, bb[1], bb[3]);
      }
    }
  }
  __syncthreads();  // all reads of sAct done before in-place epilogue writes

  if (MODE == 0) {
#pragma unroll
    for (int mt = 0; mt < 2; mt++) {
      const int r0 = cx.wm * 32 + mt * 16 + cx.grp;
#pragma unroll
      for (int nt = 0; nt < 8; nt++) {
        const int col = cx.wn * 64 + nt * 8 + cx.qp * 2;
        float bx = sbias[col], by = sbias[col + 1];
        uint32_t lo = pack2(frelu(acc[mt][nt][0] + bx), frelu(acc[mt][nt][1] + by));
        uint32_t hi = pack2(frelu(acc[mt][nt][2] + bx), frelu(acc[mt][nt][3] + by));
        *(uint32_t*)(sAct + r0 * AS + col) = lo;
        *(uint32_t*)(sAct + (r0 + 8) * AS + col) = hi;
        if (KEEPH) { hreg[mt * 16 + nt * 2] = lo; hreg[mt * 16 + nt * 2 + 1] = hi; }
      }
    }
  } else {
    const float* sWc2 = (const float*)(cx.smem + OFF_WC2);
    const float* sWn2 = (const float*)(cx.smem + OFF_WN2);
    constexpr int NJ = (MODE == 1) ? 3 : 1;
    float part[2][2][NJ];
#pragma unroll
    for (int a = 0; a < 2; a++)
#pragma unroll
      for (int b = 0; b < 2; b++)
#pragma unroll
        for (int j = 0; j < NJ; j++) part[a][b][j] = 0.0f;
#pragma unroll
    for (int mt = 0; mt < 2; mt++)
#pragma unroll
      for (int nt = 0; nt < 8; nt++) {
        const int col = cx.wn * 64 + nt * 8 + cx.qp * 2;
        float bx = sbias[col], by = sbias[col + 1];
        float v0 = frelu(acc[mt][nt][0] + bx), v1 = frelu(acc[mt][nt][1] + by);
        float v2 = frelu(acc[mt][nt][2] + bx), v3 = frelu(acc[mt][nt][3] + by);
#pragma unroll
        for (int j = 0; j < NJ; j++) {
          float w0 = (MODE == 1) ? sWc2[col * 3 + j] : sWn2[col];
          float w1 = (MODE == 1) ? sWc2[(col + 1) * 3 + j] : sWn2[col + 1];
          part[mt][0][j] += v0 * w0 + v1 * w1;
          part[mt][1][j] += v2 * w0 + v3 * w1;
        }
      }
#pragma unroll
    for (int mt = 0; mt < 2; mt++)
#pragma unroll
      for (int rh = 0; rh < 2; rh++)
#pragma unroll
        for (int j = 0; j < NJ; j++) {
          float v = part[mt][rh][j];
          v += __shfl_xor_sync(0xffffffffu, v, 1);
          v += __shfl_xor_sync(0xffffffffu, v, 2);
          if (cx.qp == 0)
            atomicAdd(&outac[(cx.wm * 32 + mt * 16 + rh * 8 + cx.grp) * 4 + j], v);
        }
    __syncthreads();
  }
}

DEV void write_h(const Ctx& cx, const uint32_t* hreg) {
  __half* sAct = (__half*)(cx.smem + OFF_ACT);
#pragma unroll
  for (int mt = 0; mt < 2; mt++) {
    const int r0 = cx.wm * 32 + mt * 16 + cx.grp;
#pragma unroll
    for (int nt = 0; nt < 8; nt++) {
      const int col = cx.wn * 64 + nt * 8 + cx.qp * 2;
      *(uint32_t*)(sAct + r0 * AS + col) = hreg[mt * 16 + nt * 2];
      *(uint32_t*)(sAct + (r0 + 8) * AS + col) = hreg[mt * 16 + nt * 2 + 1];
    }
  }
}

__global__ void __launch_bounds__(THREADS, 2) fused_mlp(Params p) {
  extern __shared__ char smem[];
  Ctx cx;
  cx.smem = smem;
  cx.tid = threadIdx.x;
  cx.lane = cx.tid & 31; cx.wid = cx.tid >> 5;
  cx.wm = cx.wid >> 2; cx.wn = cx.wid & 3;
  cx.lrow = cx.lane & 15; cx.lk = (cx.lane >> 4) << 3;
  cx.grp = cx.lane >> 2; cx.qp = cx.lane & 3;
  cx.act32 = smem_u32(smem + OFF_ACT);
  cx.wring32 = smem_u32(smem + OFF_WRING);
  cx.feat32 = smem_u32(smem + OFF_FEAT);

  const int m0 = blockIdx.x * MT;
  float* sx = (float*)(smem + OFF_SX);
  float* sB = (float*)(smem + OFF_SB);
  float* outac = (float*)(smem + OFF_OUTAC);

  if (cx.tid < 192) {
    int m = cx.tid / 3, d = cx.tid - m * 3;
    sx[m * 4 + d] = p.x[(m0 + m) * 3 + d];
  }
  for (int i = cx.tid; i < 768; i += THREADS) sB[i] = p.B[i];
  __syncthreads();

  int tbits = *p.t;
  float tval = (tbits >= 0 && tbits < (1 << 20)) ? (float)tbits : __int_as_float(tbits);
  const float tot = tval * (6000.0f / 512.0f);  // t / TAU

  uint32_t hreg[32];
  const __half* img = g_Wt + L0_IMG;

  layer<0, true,  false>(cx, g_Wt,           L0_CHUNKS, p.b0,  tot, hreg, p);
  layer<0, false, false>(cx, img + 0 * SQ_IMG, 8, p.b1,  0.f, hreg, p);
  layer<0, false, false>(cx, img + 1 * SQ_IMG, 8, p.b2,  0.f, hreg, p);
  layer<0, false, false>(cx, img + 2 * SQ_IMG, 8, p.b3,  0.f, hreg, p);
  layer<0, false, true >(cx, img + 3 * SQ_IMG, 8, p.b4,  0.f, hreg, p);  // keep h

  // sx/sB/feat are dead after L0; overlay head-final weights in the union region.
  {
    float* sWc2 = (float*)(smem + OFF_WC2);
    float* sWn2 = (float*)(smem + OFF_WN2);
    for (int i = cx.tid; i < 768; i += THREADS) sWc2[i] = p.Wc2[i];
    sWn2[cx.tid] = p.Wn2[cx.tid];
  }

  layer<0, false, false>(cx, img + 4 * SQ_IMG, 8, p.bc0, 0.f, hreg, p);
  layer<1, false, false>(cx, img + 5 * SQ_IMG, 8, p.bc1, 0.f, hreg, p);
  if (cx.tid < 192) {
    int m = cx.tid / 3, j = cx.tid - m * 3;
    p.out[(m0 + m) * 3 + j] = tanhf(outac[m * 4 + j] + p.bc2[j]) * 0.5f;
  }
  write_h(cx, hreg);
  __syncthreads();
  layer<0, false, false>(cx, img + 6 * SQ_IMG, 8, p.bn0, 0.f, hreg, p);
  layer<2, false, false>(cx, img + 7 * SQ_IMG, 8, p.bn1, 0.f, hreg, p);
  if (cx.tid < 64)
    p.out[3 * NPTS + m0 + cx.tid] = tanhf(outac[cx.tid * 4] + p.bn2[0]) * 0.1f;
}

extern "C" void kernel_launch(void* const* d_in, const int* in_sizes, int n_in,
                              void* d_out, int out_size) {
  int i = 0;
  const float* x = (const float*)d_in[i++];
  const float* B = (const float*)d_in[i++];
  const void* tp = nullptr;
  if (in_sizes[2] == 1) tp = d_in[i++];  // dict order: t at index 2
  const float *W[11], *bias[11];
  for (int j = 0; j < 11; j++) {
    W[j] = (const float*)d_in[i++];
    bias[j] = (const float*)d_in[i++];
  }
  if (!tp && i < n_in) tp = d_in[i++];

  cudaFuncSetAttribute(fused_mlp, cudaFuncAttributeMaxDynamicSharedMemorySize, SMEM_BYTES);

  constexpr int TOTAL = L0_IMG + 8 * SQ_IMG;
  prep_weights<<<(TOTAL + 255) / 256, 256>>>(W[0], W[1], W[2], W[3], W[4],
                                             W[5], W[6], W[8], W[9]);

  Params p;
  p.x = x; p.B = B;
  p.b0 = bias[0]; p.b1 = bias[1]; p.b2 = bias[2]; p.b3 = bias[3]; p.b4 = bias[4];
  p.bc0 = bias[5]; p.bc1 = bias[6]; p.bc2 = bias[7];
  p.bn0 = bias[8]; p.bn1 = bias[9]; p.bn2 = bias[10];
  p.Wc2 = W[7]; p.Wn2 = W[10];
  p.t = (const int*)tp;
  p.out = (float*)d_out;

  fused_mlp<<<NPTS / MT, THREADS, SMEM_BYTES>>>(p);
}

// round 5
// speedup vs baseline: 1.0359x; 1.0359x over previous
#include <cuda_runtime.h>
#include <cuda_fp16.h>
#include <cstdint>

#define DEV __device__ __forceinline__

namespace {
constexpr int NPTS = 131072;
constexpr int MT = 128;       // points per CTA
constexpr int THREADS = 512;  // 16 warps: 4(M) x 4(N), warp tile 32x64
constexpr int KC = 32;        // K chunk
constexpr int AS = 264;       // activation row stride (halves); 528B
constexpr int WS = 40;        // weight/feat row stride (halves); 80B
constexpr float TWO_PI = 6.2831853071795864769f;

constexpr int CH_H = 256 * WS;   // halves per weight chunk image (10240)
constexpr int CH_B = CH_H * 2;   // 20480 bytes
constexpr int L0_CHUNKS = 17;    // K0 = 544 (515 padded)
constexpr int L0_IMG = L0_CHUNKS * CH_H;
constexpr int SQ_IMG = 8 * CH_H;

// SMEM map (bytes)
constexpr int OFF_ACTA  = 0;                      // 128*264*2 = 67584
constexpr int OFF_ACTB  = 67584;                  // 67584
constexpr int OFF_WRING = 135168;                 // 3 * 20480 = 61440
constexpr int OFF_UNION = 196608;                 // L0: sx+sB | heads: Wc2+Wn2
constexpr int OFF_SX    = OFF_UNION;              // 2048 (128*4 floats)
constexpr int OFF_SB    = OFF_UNION + 2048;       // 3072
constexpr int OFF_WC2   = OFF_UNION;              // 3072
constexpr int OFF_WN2   = OFF_UNION + 3072;       // 1024
constexpr int OFF_FEAT  = 201728;                 // 2 * 10240
constexpr int OFF_BIAS  = 222208;                 // 1024
constexpr int OFF_OUTAC = 223232;                 // 2048
constexpr int SMEM_BYTES = 225280;
}

// Weight images in SMEM layout: L0 17 chunks, then 8 layers x 8 chunks of [256n][40k]
__device__ __half g_Wt[L0_IMG + 8 * SQ_IMG];

// ---------------- helpers ----------------
DEV uint32_t smem_u32(const void* p) {
  uint32_t a;
  asm("{ .reg .u64 t; cvta.to.shared.u64 t, %1; cvt.u32.u64 %0, t; }" : "=r"(a) : "l"(p));
  return a;
}
DEV void cp16(char* s, const char* g) {
  uint32_t sa = smem_u32(s);
  asm volatile("cp.async.ca.shared.global [%0], [%1], 16;" :: "r"(sa), "l"(g));
}
DEV void cp_commit() { asm volatile("cp.async.commit_group;"); }
template <int N> DEV void cp_wait() { asm volatile("cp.async.wait_group %0;" :: "n"(N)); }

DEV void ldsm4(uint32_t* r, uint32_t addr) {
  asm volatile("ldmatrix.sync.aligned.m8n8.x4.shared.b16 {%0,%1,%2,%3}, [%4];"
               : "=r"(r[0]), "=r"(r[1]), "=r"(r[2]), "=r"(r[3]) : "r"(addr));
}
DEV void mma16816(float* d, const uint32_t* a, uint32_t b0, uint32_t b1) {
  asm volatile(
      "mma.sync.aligned.m16n8k16.row.col.f32.f16.f16.f32 "
      "{%0,%1,%2,%3}, {%4,%5,%6,%7}, {%8,%9}, {%0,%1,%2,%3};\n"
      : "+f"(d[0]), "+f"(d[1]), "+f"(d[2]), "+f"(d[3])
      : "r"(a[0]), "r"(a[1]), "r"(a[2]), "r"(a[3]), "r"(b0), "r"(b1));
}
DEV float frelu(float v) { return fmaxf(v, 0.0f); }
DEV uint32_t pack2(float a, float b) {
  __half2 h = __floats2half2_rn(a, b);
  return *reinterpret_cast<uint32_t*>(&h);
}
// Cody-Waite pi reduction + polys; abs err ~4e-6, fast-math safe.
DEV void fsincos(float x, float& s, float& c) {
  float qf = rintf(x * 0.3183098861837907f);
  float r = fmaf(qf, -3.1414794921875f, x);
  r = fmaf(qf, -1.1315941810607910156e-4f, r);
  r = fmaf(qf, -1.9841872589410058936e-9f, r);
  float r2 = r * r;
  float sp = fmaf(r2, 2.7557319e-6f, -1.9841270e-4f);
  sp = fmaf(r2, sp, 8.3333333e-3f);
  sp = fmaf(r2, sp, -1.6666667e-1f);
  s = fmaf(r * r2, sp, r);
  float cp = fmaf(r2, -2.7557319e-7f, 2.4801587e-5f);
  cp = fmaf(r2, cp, -1.3888889e-3f);
  cp = fmaf(r2, cp, 4.1666667e-2f);
  cp = fmaf(r2, cp, -0.5f);
  c = fmaf(r2, cp, 1.0f);
  if (((int)qf) & 1) { s = -s; c = -c; }
}

// ---------------- prep: pack weights into SMEM-image layout ----------------
__global__ void prep_weights(const float* W0, const float* W1, const float* W2,
                             const float* W3, const float* W4, const float* Wc0,
                             const float* Wc1, const float* Wn0, const float* Wn1) {
  int e = blockIdx.x * blockDim.x + threadIdx.x;
  constexpr int TOTAL = L0_IMG + 8 * SQ_IMG;
  if (e >= TOTAL) return;
  int chunk = e / CH_H, r = e % CH_H, n = r / WS, kk = r % WS;
  float v = 0.0f;
  if (kk < KC) {
    if (chunk < L0_CHUNKS) {
      int k = chunk * KC + kk;
      if (k < 515) v = W0[k * 256 + n];
    } else {
      int c2 = chunk - L0_CHUNKS;
      int l = c2 >> 3, k = (c2 & 7) * KC + kk;
      const float* Ws[8] = {W1, W2, W3, W4, Wc0, Wc1, Wn0, Wn1};
      v = Ws[l][k * 256 + n];
    }
  }
  g_Wt[e] = __float2half(v);
}

// ---------------- fused kernel ----------------
struct Params {
  const float *x, *B;
  const float *b0, *b1, *b2, *b3, *b4, *bc0, *bc1, *bc2, *bn0, *bn1, *bn2;
  const float *Wc2, *Wn2;
  const int* t;
  float* out;
};

struct Ctx {
  char* smem;
  uint32_t wring32, feat32;
  int tid, wm, wn, lrow, lk, grp, qp, lane, wid;
};

DEV void prefetch(const Ctx& cx, const __half* gImg, int c, int slot) {
  const char* src = (const char*)(gImg + c * CH_H);
  char* dst = cx.smem + OFF_WRING + slot * CH_B;
#pragma unroll
  for (int i = 0; i < 3; i++) {
    int op = cx.tid + i * THREADS;  // 1280 x 16B
    if (op < 1280) cp16(dst + op * 16, src + op * 16);
  }
}

DEV void gen_feat(const Ctx& cx, int c, float tot) {
  const float* sx = (const float*)(cx.smem + OFF_SX);
  const float* sB = (const float*)(cx.smem + OFF_SB);
  __half* dst = (__half*)(cx.smem + OFF_FEAT + (c & 1) * 10240);
#pragma unroll
  for (int i = 0; i < 8; i++) {
    int idx = cx.tid + i * THREADS;  // 128*32
    int m = idx >> 5, kk = idx & 31, kg = c * KC + kk;
    float v = 0.0f;
    if (kg < 3) {
      v = sx[m * 4 + kg];
    } else if (kg < 515) {
      int j = (kg < 259) ? (kg - 3) : (kg - 259);
      float px = sx[m * 4] * sB[j];
      px = fmaf(sx[m * 4 + 1], sB[256 + j], px);
      px = fmaf(sx[m * 4 + 2], sB[512 + j], px);
      float sv, cv;
      fsincos(px * TWO_PI, sv, cv);
      float a = fminf(fmaxf(tot - (float)j, 0.0f), 1.0f);
      v = ((kg < 259) ? sv : cv) * a;
    }
    dst[m * WS + kk] = __float2half(v);
  }
}

// MODE 0: act -> sOut. MODE 1: dot Wc2 -> outac. MODE 2: dot Wn2 -> outac.
template <int MODE, bool L0F>
__device__ __noinline__ void layer(const Ctx& cx, const __half* gImg, int C,
                                   const float* gbias, float tot,
                                   const __half* sIn, __half* sOut) {
  float* sbias = (float*)(cx.smem + OFF_BIAS);
  float* outac = (float*)(cx.smem + OFF_OUTAC);
  const uint32_t in32 = L0F ? 0u : smem_u32(sIn);

  float acc[2][8][4];
#pragma unroll
  for (int a = 0; a < 2; a++)
#pragma unroll
    for (int b = 0; b < 8; b++)
#pragma unroll
      for (int d = 0; d < 4; d++) acc[a][b][d] = 0.0f;

  if (L0F) gen_feat(cx, 0, tot);
  prefetch(cx, gImg, 0, 0);
  cp_commit();

  for (int c = 0; c < C; c++) {
    if (c + 1 < C) {
      prefetch(cx, gImg, c + 1, (c + 1) % 3);
      cp_commit();
      cp_wait<1>();
    } else {
      cp_wait<0>();
    }
    __syncthreads();
    if (c == 0) {
      if (cx.tid < 256) sbias[cx.tid] = gbias[cx.tid];
      if (MODE != 0) outac[cx.tid] = 0.0f;
    }
    if (L0F && c + 1 < C) gen_feat(cx, c + 1, tot);

    const uint32_t aBase = L0F ? (cx.feat32 + (c & 1) * 10240) : in32;
    const int ast = L0F ? WS : AS;
    const int kb = L0F ? 0 : c * KC;
    const uint32_t wslot = cx.wring32 + (c % 3) * CH_B;

#pragma unroll
    for (int ks = 0; ks < KC; ks += 16) {
      uint32_t a0[4], a1[4];
      uint32_t aA = aBase + ((cx.wm * 32 + cx.lrow) * ast + kb + ks + cx.lk) * 2;
      ldsm4(a0, aA);
      ldsm4(a1, aA + 16 * ast * 2);
      uint32_t bA = wslot + ((cx.wn * 64 + cx.lrow) * WS + ks + cx.lk) * 2;
#pragma unroll
      for (int np = 0; np < 4; np++) {
        uint32_t bb[4];
        ldsm4(bb, bA + np * (16 * WS * 2));
        mma16816(acc[0][2 * np],     a0, bb[0], bb[2]);
        mma16816(acc[0][2 * np + 1], a0, bb[1], bb[3]);
        mma16816(acc[1][2 * np],     a1, bb[0], bb[2]);
        mma16816(acc[1][2 * np + 1], a1, bb[1], bb[3]);
      }
    }
  }
  __syncthreads();  // all fragment reads done (sOut may alias next layer's sIn)

  if (MODE == 0) {
#pragma unroll
    for (int mt = 0; mt < 2; mt++) {
      const int r0 = cx.wm * 32 + mt * 16 + cx.grp;
#pragma unroll
      for (int nt = 0; nt < 8; nt++) {
        const int col = cx.wn * 64 + nt * 8 + cx.qp * 2;
        float bx = sbias[col], by = sbias[col + 1];
        *(uint32_t*)(sOut + r0 * AS + col) =
            pack2(frelu(acc[mt][nt][0] + bx), frelu(acc[mt][nt][1] + by));
        *(uint32_t*)(sOut + (r0 + 8) * AS + col) =
            pack2(frelu(acc[mt][nt][2] + bx), frelu(acc[mt][nt][3] + by));
      }
    }
    __syncthreads();
  } else {
    const float* sWc2 = (const float*)(cx.smem + OFF_WC2);
    const float* sWn2 = (const float*)(cx.smem + OFF_WN2);
    constexpr int NJ = (MODE == 1) ? 3 : 1;
    float part[2][2][NJ];
#pragma unroll
    for (int a = 0; a < 2; a++)
#pragma unroll
      for (int b = 0; b < 2; b++)
#pragma unroll
        for (int j = 0; j < NJ; j++) part[a][b][j] = 0.0f;
#pragma unroll
    for (int mt = 0; mt < 2; mt++)
#pragma unroll
      for (int nt = 0; nt < 8; nt++) {
        const int col = cx.wn * 64 + nt * 8 + cx.qp * 2;
        float bx = sbias[col], by = sbias[col + 1];
        float v0 = frelu(acc[mt][nt][0] + bx), v1 = frelu(acc[mt][nt][1] + by);
        float v2 = frelu(acc[mt][nt][2] + bx), v3 = frelu(acc[mt][nt][3] + by);
#pragma unroll
        for (int j = 0; j < NJ; j++) {
          float w0 = (MODE == 1) ? sWc2[col * 3 + j] : sWn2[col];
          float w1 = (MODE == 1) ? sWc2[(col + 1) * 3 + j] : sWn2[col + 1];
          part[mt][0][j] += v0 * w0 + v1 * w1;
          part[mt][1][j] += v2 * w0 + v3 * w1;
        }
      }
#pragma unroll
    for (int mt = 0; mt < 2; mt++)
#pragma unroll
      for (int rh = 0; rh < 2; rh++)
#pragma unroll
        for (int j = 0; j < NJ; j++) {
          float v = part[mt][rh][j];
          v += __shfl_xor_sync(0xffffffffu, v, 1);
          v += __shfl_xor_sync(0xffffffffu, v, 2);
          if (cx.qp == 0)
            atomicAdd(&outac[(cx.wm * 32 + mt * 16 + rh * 8 + cx.grp) * 4 + j], v);
        }
    __syncthreads();
  }
}

__global__ void __launch_bounds__(THREADS, 1) fused_mlp(Params p) {
  extern __shared__ char smem[];
  Ctx cx;
  cx.smem = smem;
  cx.tid = threadIdx.x;
  cx.lane = cx.tid & 31; cx.wid = cx.tid >> 5;
  cx.wm = cx.wid >> 2; cx.wn = cx.wid & 3;
  cx.lrow = cx.lane & 15; cx.lk = (cx.lane >> 4) << 3;
  cx.grp = cx.lane >> 2; cx.qp = cx.lane & 3;
  cx.wring32 = smem_u32(smem + OFF_WRING);
  cx.feat32 = smem_u32(smem + OFF_FEAT);

  const int m0 = blockIdx.x * MT;
  float* sx = (float*)(smem + OFF_SX);
  float* sB = (float*)(smem + OFF_SB);
  float* outac = (float*)(smem + OFF_OUTAC);
  __half* actA = (__half*)(smem + OFF_ACTA);
  __half* actB = (__half*)(smem + OFF_ACTB);

  if (cx.tid < 384) {
    int m = cx.tid / 3, d = cx.tid - m * 3;
    sx[m * 4 + d] = p.x[(m0 + m) * 3 + d];
  }
  for (int i = cx.tid; i < 768; i += THREADS) sB[i] = p.B[i];
  __syncthreads();

  int tbits = *p.t;
  float tval = (tbits >= 0 && tbits < (1 << 20)) ? (float)tbits : __int_as_float(tbits);
  const float tot = tval * (6000.0f / 512.0f);  // t / TAU

  const __half* img = g_Wt + L0_IMG;

  layer<0, true >(cx, g_Wt,             L0_CHUNKS, p.b0, tot, nullptr, actA);
  layer<0, false>(cx, img + 0 * SQ_IMG, 8, p.b1,  0.f, actA, actB);
  layer<0, false>(cx, img + 1 * SQ_IMG, 8, p.b2,  0.f, actB, actA);
  layer<0, false>(cx, img + 2 * SQ_IMG, 8, p.b3,  0.f, actA, actB);
  layer<0, false>(cx, img + 3 * SQ_IMG, 8, p.b4,  0.f, actB, actA);  // h -> actA

  // sx/sB/feat dead after L0: overlay head-final weights in the union region.
  {
    float* sWc2 = (float*)(smem + OFF_WC2);
    float* sWn2 = (float*)(smem + OFF_WN2);
    for (int i = cx.tid; i < 768; i += THREADS) sWc2[i] = p.Wc2[i];
    if (cx.tid < 256) sWn2[cx.tid] = p.Wn2[cx.tid];
  }

  layer<0, false>(cx, img + 4 * SQ_IMG, 8, p.bc0, 0.f, actA, actB);
  layer<1, false>(cx, img + 5 * SQ_IMG, 8, p.bc1, 0.f, actB, nullptr);
  if (cx.tid < 384) {
    int m = cx.tid / 3, j = cx.tid - m * 3;
    p.out[(m0 + m) * 3 + j] = tanhf(outac[m * 4 + j] + p.bc2[j]) * 0.5f;
  }
  layer<0, false>(cx, img + 6 * SQ_IMG, 8, p.bn0, 0.f, actA, actB);  // h intact in actA
  layer<2, false>(cx, img + 7 * SQ_IMG, 8, p.bn1, 0.f, actB, nullptr);
  if (cx.tid < 128)
    p.out[3 * NPTS + m0 + cx.tid] = tanhf(outac[cx.tid * 4] + p.bn2[0]) * 0.1f;
}

extern "C" void kernel_launch(void* const* d_in, const int* in_sizes, int n_in,
                              void* d_out, int out_size) {
  int i = 0;
  const float* x = (const float*)d_in[i++];
  const float* B = (const float*)d_in[i++];
  const void* tp = nullptr;
  if (in_sizes[2] == 1) tp = d_in[i++];  // dict order: t at index 2
  const float *W[11], *bias[11];
  for (int j = 0; j < 11; j++) {
    W[j] = (const float*)d_in[i++];
    bias[j] = (const float*)d_in[i++];
  }
  if (!tp && i < n_in) tp = d_in[i++];

  cudaFuncSetAttribute(fused_mlp, cudaFuncAttributeMaxDynamicSharedMemorySize, SMEM_BYTES);

  constexpr int TOTAL = L0_IMG + 8 * SQ_IMG;
  prep_weights<<<(TOTAL + 255) / 256, 256>>>(W[0], W[1], W[2], W[3], W[4],
                                             W[5], W[6], W[8], W[9]);

  Params p;
  p.x = x; p.B = B;
  p.b0 = bias[0]; p.b1 = bias[1]; p.b2 = bias[2]; p.b3 = bias[3]; p.b4 = bias[4];
  p.bc0 = bias[5]; p.bc1 = bias[6]; p.bc2 = bias[7];
  p.bn0 = bias[8]; p.bn1 = bias[9]; p.bn2 = bias[10];
  p.Wc2 = W[7]; p.Wn2 = W[10];
  p.t = (const int*)tp;
  p.out = (float*)d_out;

  fused_mlp<<<NPTS / MT, THREADS, SMEM_BYTES>>>(p);
}

// round 6
// speedup vs baseline: 1.0688x; 1.0318x over previous
#include <cuda_runtime.h>
#include <cuda_fp16.h>
#include <cstdint>

#define DEV __device__ __forceinline__

namespace {
constexpr int NPTS = 131072;
constexpr int MT = 128;       // points per CTA
constexpr int THREADS = 512;  // 16 warps: 4(M) x 4(N), warp tile 32x64
constexpr int KC = 32;        // K chunk
constexpr int AS = 264;       // activation row stride (halves); 528B
constexpr int WS = 40;        // weight/feat row stride (halves); 80B
constexpr float TWO_PI = 6.2831853071795864769f;

constexpr int CH_H = 256 * WS;    // halves per weight chunk image (10240)
constexpr uint32_t CH_B = CH_H * 2;  // 20480 bytes
constexpr int L0_CHUNKS = 17;     // K0 = 544 (515 padded)
constexpr int L0_IMG = L0_CHUNKS * CH_H;
constexpr int SQ_IMG = 8 * CH_H;

// SMEM map (bytes)
constexpr int OFF_ACTA  = 0;                 // 67584
constexpr int OFF_ACTB  = 67584;             // 67584
constexpr int OFF_WRING = 135168;            // 3 * 20480
constexpr int OFF_UNION = 196608;            // L0: sx+sB | heads: Wc2+Wn2
constexpr int OFF_SX    = OFF_UNION;
constexpr int OFF_SB    = OFF_UNION + 2048;
constexpr int OFF_WC2   = OFF_UNION;
constexpr int OFF_WN2   = OFF_UNION + 3072;
constexpr int OFF_FEAT  = 201728;            // 2 * 10240
constexpr int OFF_BIAS  = 222208;            // 1024
constexpr int OFF_OUTAC = 223232;            // 2048
constexpr int OFF_MBAR  = 225280;            // 3 x 8
constexpr int SMEM_BYTES = 225344;
}

// Weight images in SMEM layout: L0 17 chunks, then 8 layers x 8 chunks of [256n][40k]
__device__ __half g_Wt[L0_IMG + 8 * SQ_IMG];

// ---------------- helpers ----------------
DEV uint32_t smem_u32(const void* p) {
  uint32_t a;
  asm("{ .reg .u64 t; cvta.to.shared.u64 t, %1; cvt.u32.u64 %0, t; }" : "=r"(a) : "l"(p));
  return a;
}
#define MBAR_INIT(mb, c) \
  asm volatile("mbarrier.init.shared.b64 [%0], %1;" :: "r"(mb), "r"(c) : "memory")
#define MBAR_WAIT(mb, ph) do {                                                        \
  uint32_t _m = (mb), _p = (uint32_t)(ph), _d;                                        \
  asm volatile("{ .reg .pred p; mbarrier.try_wait.parity.acquire.cta.shared::cta.b64 p, [%1], %2; selp.b32 %0,1,0,p; }" \
               : "=r"(_d) : "r"(_m), "r"(_p) : "memory");                             \
  if (!_d) {                                                                          \
    asm volatile("{ .reg .pred P1; WL%=: mbarrier.try_wait.parity.acquire.cta.shared::cta.b64 P1, [%0], %1, 0x989680; @P1 bra.uni WD%=; bra.uni WL%=; WD%=: }" \
                 :: "r"(_m), "r"(_p) : "memory");                                     \
  }                                                                                   \
} while (0)

DEV void issue_chunk(uint32_t dst32, const void* src, uint32_t mbar) {
  asm volatile("mbarrier.arrive.expect_tx.shared.b64 _, [%0], %1;"
               :: "r"(mbar), "r"(CH_B) : "memory");
  asm volatile(
      "cp.async.bulk.shared::cta.global.mbarrier::complete_tx::bytes [%0], [%1], %2, [%3];"
      :: "r"(dst32), "l"(src), "r"(CH_B), "r"(mbar) : "memory");
}

DEV void ldsm4(uint32_t* r, uint32_t addr) {
  asm volatile("ldmatrix.sync.aligned.m8n8.x4.shared.b16 {%0,%1,%2,%3}, [%4];"
               : "=r"(r[0]), "=r"(r[1]), "=r"(r[2]), "=r"(r[3]) : "r"(addr));
}
DEV void mma16816(float* d, const uint32_t* a, uint32_t b0, uint32_t b1) {
  asm volatile(
      "mma.sync.aligned.m16n8k16.row.col.f32.f16.f16.f32 "
      "{%0,%1,%2,%3}, {%4,%5,%6,%7}, {%8,%9}, {%0,%1,%2,%3};\n"
      : "+f"(d[0]), "+f"(d[1]), "+f"(d[2]), "+f"(d[3])
      : "r"(a[0]), "r"(a[1]), "r"(a[2]), "r"(a[3]), "r"(b0), "r"(b1));
}
DEV float frelu(float v) { return fmaxf(v, 0.0f); }
DEV uint32_t pack2(float a, float b) {
  __half2 h = __floats2half2_rn(a, b);
  return *reinterpret_cast<uint32_t*>(&h);
}
// Cody-Waite pi reduction + polys; abs err ~4e-6, fast-math safe.
DEV void fsincos(float x, float& s, float& c) {
  float qf = rintf(x * 0.3183098861837907f);
  float r = fmaf(qf, -3.1414794921875f, x);
  r = fmaf(qf, -1.1315941810607910156e-4f, r);
  r = fmaf(qf, -1.9841872589410058936e-9f, r);
  float r2 = r * r;
  float sp = fmaf(r2, 2.7557319e-6f, -1.9841270e-4f);
  sp = fmaf(r2, sp, 8.3333333e-3f);
  sp = fmaf(r2, sp, -1.6666667e-1f);
  s = fmaf(r * r2, sp, r);
  float cp = fmaf(r2, -2.7557319e-7f, 2.4801587e-5f);
  cp = fmaf(r2, cp, -1.3888889e-3f);
  cp = fmaf(r2, cp, 4.1666667e-2f);
  cp = fmaf(r2, cp, -0.5f);
  c = fmaf(r2, cp, 1.0f);
  if (((int)qf) & 1) { s = -s; c = -c; }
}

// ---------------- prep: pack weights into SMEM-image layout ----------------
__global__ void prep_weights(const float* W0, const float* W1, const float* W2,
                             const float* W3, const float* W4, const float* Wc0,
                             const float* Wc1, const float* Wn0, const float* Wn1) {
  int e = blockIdx.x * blockDim.x + threadIdx.x;
  constexpr int TOTAL = L0_IMG + 8 * SQ_IMG;
  if (e >= TOTAL) return;
  int chunk = e / CH_H, r = e % CH_H, n = r / WS, kk = r % WS;
  float v = 0.0f;
  if (kk < KC) {
    if (chunk < L0_CHUNKS) {
      int k = chunk * KC + kk;
      if (k < 515) v = W0[k * 256 + n];
    } else {
      int c2 = chunk - L0_CHUNKS;
      int l = c2 >> 3, k = (c2 & 7) * KC + kk;
      const float* Ws[8] = {W1, W2, W3, W4, Wc0, Wc1, Wn0, Wn1};
      v = Ws[l][k * 256 + n];
    }
  }
  g_Wt[e] = __float2half(v);
}

// ---------------- fused kernel ----------------
struct Params {
  const float *x, *B;
  const float *b0, *b1, *b2, *b3, *b4, *bc0, *bc1, *bc2, *bn0, *bn1, *bn2;
  const float *Wc2, *Wn2;
  const int* t;
  float* out;
};

struct Ctx {
  char* smem;
  uint32_t wring32, feat32, mbar32;
  int tid, wm, wn, lrow, lk, grp, qp, lane, wid;
};

DEV void gen_feat(const Ctx& cx, int c, float tot) {
  const float* sx = (const float*)(cx.smem + OFF_SX);
  const float* sB = (const float*)(cx.smem + OFF_SB);
  __half* dst = (__half*)(cx.smem + OFF_FEAT + (c & 1) * 10240);
#pragma unroll
  for (int i = 0; i < 8; i++) {
    int idx = cx.tid + i * THREADS;  // 128*32
    int m = idx >> 5, kk = idx & 31, kg = c * KC + kk;
    float v = 0.0f;
    if (kg < 3) {
      v = sx[m * 4 + kg];
    } else if (kg < 515) {
      int j = (kg < 259) ? (kg - 3) : (kg - 259);
      float px = sx[m * 4] * sB[j];
      px = fmaf(sx[m * 4 + 1], sB[256 + j], px);
      px = fmaf(sx[m * 4 + 2], sB[512 + j], px);
      float sv, cv;
      fsincos(px * TWO_PI, sv, cv);
      float a = fminf(fmaxf(tot - (float)j, 0.0f), 1.0f);
      v = ((kg < 259) ? sv : cv) * a;
    }
    dst[m * WS + kk] = __float2half(v);
  }
}

// MODE 0: act -> sOut. MODE 1: dot Wc2 -> outac. MODE 2: dot Wn2 -> outac.
// FIRST: issue own chunk 0 (otherwise predecessor issued it).
template <int MODE, bool L0F, bool FIRST>
__device__ __noinline__ void layer(const Ctx& cx, const __half* gImg, int C,
                                   const float* gbias, float tot,
                                   const __half* sIn, __half* sOut,
                                   const __half* nextImg, int* ph) {
  float* sbias = (float*)(cx.smem + OFF_BIAS);
  float* outac = (float*)(cx.smem + OFF_OUTAC);
  const uint32_t in32 = L0F ? 0u : smem_u32(sIn);

  float acc[2][8][4];
#pragma unroll
  for (int a = 0; a < 2; a++)
#pragma unroll
    for (int b = 0; b < 8; b++)
#pragma unroll
      for (int d = 0; d < 4; d++) acc[a][b][d] = 0.0f;

  if (FIRST && cx.tid == 0) issue_chunk(cx.wring32, gImg, cx.mbar32);
  if (L0F) gen_feat(cx, 0, tot);

  for (int c = 0; c < C; c++) {
    const int s = c % 3;
    MBAR_WAIT(cx.mbar32 + s * 8, ph[s]);
    ph[s] ^= 1;
    __syncthreads();  // bound warp skew to 1 chunk before slot reuse
    if (cx.tid == 0) {
      if (c + 1 < C) {
        int s2 = (c + 1) % 3;
        issue_chunk(cx.wring32 + s2 * CH_B, gImg + (c + 1) * CH_H, cx.mbar32 + s2 * 8);
      } else if (nextImg) {
        issue_chunk(cx.wring32, nextImg, cx.mbar32);  // next layer chunk 0 -> slot 0
      }
    }
    if (c == 0) {
      if (cx.tid < 256) sbias[cx.tid] = gbias[cx.tid];
      if (MODE != 0) outac[cx.tid] = 0.0f;
    }
    if (L0F && c + 1 < C) gen_feat(cx, c + 1, tot);

    const uint32_t aBase = L0F ? (cx.feat32 + (c & 1) * 10240) : in32;
    const int ast = L0F ? WS : AS;
    const int kb = L0F ? 0 : c * KC;
    const uint32_t wslot = cx.wring32 + s * CH_B;
    const uint32_t aA0 = aBase + ((cx.wm * 32 + cx.lrow) * ast + kb + cx.lk) * 2;
    const uint32_t bA0 = wslot + ((cx.wn * 64 + cx.lrow) * WS + cx.lk) * 2;

#pragma unroll
    for (int ks = 0; ks < KC; ks += 16) {
      uint32_t a0[4], a1[4];
      ldsm4(a0, aA0 + ks * 2);
      ldsm4(a1, aA0 + ks * 2 + 16 * ast * 2);
#pragma unroll
      for (int np = 0; np < 4; np++) {
        uint32_t bb[4];
        ldsm4(bb, bA0 + ks * 2 + np * (16 * WS * 2));
        mma16816(acc[0][2 * np],     a0, bb[0], bb[2]);
        mma16816(acc[0][2 * np + 1], a0, bb[1], bb[3]);
        mma16816(acc[1][2 * np],     a1, bb[0], bb[2]);
        mma16816(acc[1][2 * np + 1], a1, bb[1], bb[3]);
      }
    }
  }
  __syncthreads();  // all fragment reads done (sOut may alias next layer's sIn)

  if (MODE == 0) {
#pragma unroll
    for (int mt = 0; mt < 2; mt++) {
      const int r0 = cx.wm * 32 + mt * 16 + cx.grp;
#pragma unroll
      for (int nt = 0; nt < 8; nt++) {
        const int col = cx.wn * 64 + nt * 8 + cx.qp * 2;
        float bx = sbias[col], by = sbias[col + 1];
        *(uint32_t*)(sOut + r0 * AS + col) =
            pack2(frelu(acc[mt][nt][0] + bx), frelu(acc[mt][nt][1] + by));
        *(uint32_t*)(sOut + (r0 + 8) * AS + col) =
            pack2(frelu(acc[mt][nt][2] + bx), frelu(acc[mt][nt][3] + by));
      }
    }
    __syncthreads();
  } else {
    const float* sWc2 = (const float*)(cx.smem + OFF_WC2);
    const float* sWn2 = (const float*)(cx.smem + OFF_WN2);
    constexpr int NJ = (MODE == 1) ? 3 : 1;
    float part[2][2][NJ];
#pragma unroll
    for (int a = 0; a < 2; a++)
#pragma unroll
      for (int b = 0; b < 2; b++)
#pragma unroll
        for (int j = 0; j < NJ; j++) part[a][b][j] = 0.0f;
#pragma unroll
    for (int mt = 0; mt < 2; mt++)
#pragma unroll
      for (int nt = 0; nt < 8; nt++) {
        const int col = cx.wn * 64 + nt * 8 + cx.qp * 2;
        float bx = sbias[col], by = sbias[col + 1];
        float v0 = frelu(acc[mt][nt][0] + bx), v1 = frelu(acc[mt][nt][1] + by);
        float v2 = frelu(acc[mt][nt][2] + bx), v3 = frelu(acc[mt][nt][3] + by);
#pragma unroll
        for (int j = 0; j < NJ; j++) {
          float w0 = (MODE == 1) ? sWc2[col * 3 + j] : sWn2[col];
          float w1 = (MODE == 1) ? sWc2[(col + 1) * 3 + j] : sWn2[col + 1];
          part[mt][0][j] += v0 * w0 + v1 * w1;
          part[mt][1][j] += v2 * w0 + v3 * w1;
        }
      }
#pragma unroll
    for (int mt = 0; mt < 2; mt++)
#pragma unroll
      for (int rh = 0; rh < 2; rh++)
#pragma unroll
        for (int j = 0; j < NJ; j++) {
          float v = part[mt][rh][j];
          v += __shfl_xor_sync(0xffffffffu, v, 1);
          v += __shfl_xor_sync(0xffffffffu, v, 2);
          if (cx.qp == 0)
            atomicAdd(&outac[(cx.wm * 32 + mt * 16 + rh * 8 + cx.grp) * 4 + j], v);
        }
    __syncthreads();
  }
}

__global__ void __launch_bounds__(THREADS, 1) fused_mlp(Params p) {
  extern __shared__ char smem[];
  Ctx cx;
  cx.smem = smem;
  cx.tid = threadIdx.x;
  cx.lane = cx.tid & 31; cx.wid = cx.tid >> 5;
  cx.wm = cx.wid >> 2; cx.wn = cx.wid & 3;
  cx.lrow = cx.lane & 15; cx.lk = (cx.lane >> 4) << 3;
  cx.grp = cx.lane >> 2; cx.qp = cx.lane & 3;
  cx.wring32 = smem_u32(smem + OFF_WRING);
  cx.feat32 = smem_u32(smem + OFF_FEAT);
  cx.mbar32 = smem_u32(smem + OFF_MBAR);

  const int m0 = blockIdx.x * MT;
  float* sx = (float*)(smem + OFF_SX);
  float* sB = (float*)(smem + OFF_SB);
  float* outac = (float*)(smem + OFF_OUTAC);
  __half* actA = (__half*)(smem + OFF_ACTA);
  __half* actB = (__half*)(smem + OFF_ACTB);

  if (cx.tid == 0) {
    MBAR_INIT(cx.mbar32, 1);
    MBAR_INIT(cx.mbar32 + 8, 1);
    MBAR_INIT(cx.mbar32 + 16, 1);
  }
  if (cx.tid < 384) {
    int m = cx.tid / 3, d = cx.tid - m * 3;
    sx[m * 4 + d] = p.x[(m0 + m) * 3 + d];
  }
  for (int i = cx.tid; i < 768; i += THREADS) sB[i] = p.B[i];
  __syncthreads();

  int tbits = *p.t;
  float tval = (tbits >= 0 && tbits < (1 << 20)) ? (float)tbits : __int_as_float(tbits);
  const float tot = tval * (6000.0f / 512.0f);  // t / TAU

  int ph[3] = {0, 0, 0};
  const __half* img = g_Wt + L0_IMG;

  layer<0, true,  true >(cx, g_Wt, L0_CHUNKS, p.b0, tot, nullptr, actA, img, ph);
  layer<0, false, false>(cx, img + 0 * SQ_IMG, 8, p.b1,  0.f, actA, actB, img + 1 * SQ_IMG, ph);
  layer<0, false, false>(cx, img + 1 * SQ_IMG, 8, p.b2,  0.f, actB, actA, img + 2 * SQ_IMG, ph);
  layer<0, false, false>(cx, img + 2 * SQ_IMG, 8, p.b3,  0.f, actA, actB, img + 3 * SQ_IMG, ph);
  layer<0, false, false>(cx, img + 3 * SQ_IMG, 8, p.b4,  0.f, actB, actA, img + 4 * SQ_IMG, ph);  // h -> actA

  // sx/sB/feat dead after L0: overlay head-final weights in the union region.
  {
    float* sWc2 = (float*)(smem + OFF_WC2);
    float* sWn2 = (float*)(smem + OFF_WN2);
    for (int i = cx.tid; i < 768; i += THREADS) sWc2[i] = p.Wc2[i];
    if (cx.tid < 256) sWn2[cx.tid] = p.Wn2[cx.tid];
  }

  layer<0, false, false>(cx, img + 4 * SQ_IMG, 8, p.bc0, 0.f, actA, actB, img + 5 * SQ_IMG, ph);
  layer<1, false, false>(cx, img + 5 * SQ_IMG, 8, p.bc1, 0.f, actB, nullptr, img + 6 * SQ_IMG, ph);
  if (cx.tid < 384) {
    int m = cx.tid / 3, j = cx.tid - m * 3;
    p.out[(m0 + m) * 3 + j] = tanhf(outac[m * 4 + j] + p.bc2[j]) * 0.5f;
  }
  layer<0, false, false>(cx, img + 6 * SQ_IMG, 8, p.bn0, 0.f, actA, actB, img + 7 * SQ_IMG, ph);  // h intact in actA
  layer<2, false, false>(cx, img + 7 * SQ_IMG, 8, p.bn1, 0.f, actB, nullptr, nullptr, ph);
  if (cx.tid < 128)
    p.out[3 * NPTS + m0 + cx.tid] = tanhf(outac[cx.tid * 4] + p.bn2[0]) * 0.1f;
}

extern "C" void kernel_launch(void* const* d_in, const int* in_sizes, int n_in,
                              void* d_out, int out_size) {
  int i = 0;
  const float* x = (const float*)d_in[i++];
  const float* B = (const float*)d_in[i++];
  const void* tp = nullptr;
  if (in_sizes[2] == 1) tp = d_in[i++];  // dict order: t at index 2
  const float *W[11], *bias[11];
  for (int j = 0; j < 11; j++) {
    W[j] = (const float*)d_in[i++];
    bias[j] = (const float*)d_in[i++];
  }
  if (!tp && i < n_in) tp = d_in[i++];

  cudaFuncSetAttribute(fused_mlp, cudaFuncAttributeMaxDynamicSharedMemorySize, SMEM_BYTES);

  constexpr int TOTAL = L0_IMG + 8 * SQ_IMG;
  prep_weights<<<(TOTAL + 255) / 256, 256>>>(W[0], W[1], W[2], W[3], W[4],
                                             W[5], W[6], W[8], W[9]);

  Params p;
  p.x = x; p.B = B;
  p.b0 = bias[0]; p.b1 = bias[1]; p.b2 = bias[2]; p.b3 = bias[3]; p.b4 = bias[4];
  p.bc0 = bias[5]; p.bc1 = bias[6]; p.bc2 = bias[7];
  p.bn0 = bias[8]; p.bn1 = bias[9]; p.bn2 = bias[10];
  p.Wc2 = W[7]; p.Wn2 = W[10];
  p.t = (const int*)tp;
  p.out = (float*)d_out;

  fused_mlp<<<NPTS / MT, THREADS, SMEM_BYTES>>>(p);
}

// round 7
// speedup vs baseline: 1.3687x; 1.2806x over previous
#include <cuda_runtime.h>
#include <cuda_fp16.h>
#include <cstdint>

#define DEV __device__ __forceinline__

namespace {
constexpr int NPTS = 131072;
constexpr int MT = 128;       // points per CTA
constexpr int THREADS = 544;  // 16 compute warps (4Mx4N) + 1 producer warp
constexpr int CTH = 512;      // compute threads
constexpr int KC = 32;        // K chunk
constexpr int AS = 264;       // activation row stride (halves); 528B
constexpr int WS = 40;        // weight/feat row stride (halves); 80B
constexpr float TWO_PI = 6.2831853071795864769f;

constexpr int CH_H = 256 * WS;       // halves per weight chunk (10240)
constexpr uint32_t CH_B = CH_H * 2;  // 20480 bytes
constexpr int L0_CHUNKS = 17;        // K0 = 544 (515 padded)
constexpr int N_CHUNKS = L0_CHUNKS + 64;  // 81 flat chunks

// SMEM map (bytes)
constexpr int OFF_ACTA  = 0;                 // 67584
constexpr int OFF_ACTB  = 67584;             // 67584
constexpr int OFF_WRING = 135168;            // 3 * 20480
constexpr int OFF_UNION = 196608;            // L0: sx+sB | heads: Wc2+Wn2
constexpr int OFF_SX    = OFF_UNION;
constexpr int OFF_SB    = OFF_UNION + 2048;
constexpr int OFF_WC2   = OFF_UNION;
constexpr int OFF_WN2   = OFF_UNION + 3072;
constexpr int OFF_FEAT  = 201728;            // 2 * 10240
constexpr int OFF_BIAS  = 222208;            // 2 x 1024 (double-buffered)
constexpr int OFF_OUTAC = 224256;            // 2048
constexpr int OFF_FULL  = 226304;            // 3 x 8
constexpr int OFF_EMPTY = 226328;            // 3 x 8
constexpr int SMEM_BYTES = 226368;
}

// Weight images, flat: chunk i at g_Wt + i*CH_H. L0 = chunks 0..16, layer l = 17+8(l-1)..
__device__ __half g_Wt[(size_t)N_CHUNKS * CH_H];

// ---------------- helpers ----------------
DEV uint32_t smem_u32(const void* p) {
  uint32_t a;
  asm("{ .reg .u64 t; cvta.to.shared.u64 t, %1; cvt.u32.u64 %0, t; }" : "=r"(a) : "l"(p));
  return a;
}
#define MBAR_INIT(mb, c) \
  asm volatile("mbarrier.init.shared.b64 [%0], %1;" :: "r"(mb), "r"(c) : "memory")
#define MBAR_ARRIVE(mb) \
  asm volatile("mbarrier.arrive.shared.b64 _, [%0];" :: "r"(mb) : "memory")
#define MBAR_WAIT(mb, ph) do {                                                        \
  uint32_t _m = (mb), _p = (uint32_t)(ph), _d;                                        \
  asm volatile("{ .reg .pred p; mbarrier.try_wait.parity.acquire.cta.shared::cta.b64 p, [%1], %2; selp.b32 %0,1,0,p; }" \
               : "=r"(_d) : "r"(_m), "r"(_p) : "memory");                             \
  if (!_d) {                                                                          \
    asm volatile("{ .reg .pred P1; WL%=: mbarrier.try_wait.parity.acquire.cta.shared::cta.b64 P1, [%0], %1, 0x989680; @P1 bra.uni WD%=; bra.uni WL%=; WD%=: }" \
                 :: "r"(_m), "r"(_p) : "memory");                                     \
  }                                                                                   \
} while (0)

DEV void barsync() { asm volatile("bar.sync 1, 512;" ::: "memory"); }  // compute warps only

DEV void issue_chunk(uint32_t dst32, const void* src, uint32_t mbar) {
  asm volatile("mbarrier.arrive.expect_tx.shared.b64 _, [%0], %1;"
               :: "r"(mbar), "r"(CH_B) : "memory");
  asm volatile(
      "cp.async.bulk.shared::cta.global.mbarrier::complete_tx::bytes [%0], [%1], %2, [%3];"
      :: "r"(dst32), "l"(src), "r"(CH_B), "r"(mbar) : "memory");
}

DEV void ldsm4(uint32_t* r, uint32_t addr) {
  asm volatile("ldmatrix.sync.aligned.m8n8.x4.shared.b16 {%0,%1,%2,%3}, [%4];"
               : "=r"(r[0]), "=r"(r[1]), "=r"(r[2]), "=r"(r[3]) : "r"(addr));
}
DEV void mma16816(float* d, const uint32_t* a, uint32_t b0, uint32_t b1) {
  asm volatile(
      "mma.sync.aligned.m16n8k16.row.col.f32.f16.f16.f32 "
      "{%0,%1,%2,%3}, {%4,%5,%6,%7}, {%8,%9}, {%0,%1,%2,%3};\n"
      : "+f"(d[0]), "+f"(d[1]), "+f"(d[2]), "+f"(d[3])
      : "r"(a[0]), "r"(a[1]), "r"(a[2]), "r"(a[3]), "r"(b0), "r"(b1));
}
DEV float frelu(float v) { return fmaxf(v, 0.0f); }
DEV uint32_t pack2(float a, float b) {
  __half2 h = __floats2half2_rn(a, b);
  return *reinterpret_cast<uint32_t*>(&h);
}
// Cody-Waite pi reduction + polys; abs err ~4e-6, fast-math safe.
DEV void fsincos(float x, float& s, float& c) {
  float qf = rintf(x * 0.3183098861837907f);
  float r = fmaf(qf, -3.1414794921875f, x);
  r = fmaf(qf, -1.1315941810607910156e-4f, r);
  r = fmaf(qf, -1.9841872589410058936e-9f, r);
  float r2 = r * r;
  float sp = fmaf(r2, 2.7557319e-6f, -1.9841270e-4f);
  sp = fmaf(r2, sp, 8.3333333e-3f);
  sp = fmaf(r2, sp, -1.6666667e-1f);
  s = fmaf(r * r2, sp, r);
  float cp = fmaf(r2, -2.7557319e-7f, 2.4801587e-5f);
  cp = fmaf(r2, cp, -1.3888889e-3f);
  cp = fmaf(r2, cp, 4.1666667e-2f);
  cp = fmaf(r2, cp, -0.5f);
  c = fmaf(r2, cp, 1.0f);
  if (((int)qf) & 1) { s = -s; c = -c; }
}

// ---------------- prep: pack weights into SMEM-image layout ----------------
__global__ void prep_weights(const float* W0, const float* W1, const float* W2,
                             const float* W3, const float* W4, const float* Wc0,
                             const float* Wc1, const float* Wn0, const float* Wn1) {
  int e = blockIdx.x * blockDim.x + threadIdx.x;
  constexpr int TOTAL = N_CHUNKS * CH_H;
  if (e >= TOTAL) return;
  int chunk = e / CH_H, r = e % CH_H, n = r / WS, kk = r % WS;
  float v = 0.0f;
  if (kk < KC) {
    if (chunk < L0_CHUNKS) {
      int k = chunk * KC + kk;
      if (k < 515) v = W0[k * 256 + n];
    } else {
      int c2 = chunk - L0_CHUNKS;
      int l = c2 >> 3, k = (c2 & 7) * KC + kk;
      const float* Ws[8] = {W1, W2, W3, W4, Wc0, Wc1, Wn0, Wn1};
      v = Ws[l][k * 256 + n];
    }
  }
  g_Wt[e] = __float2half(v);
}

// ---------------- fused kernel ----------------
struct Params {
  const float *x, *B;
  const float *b0, *b1, *b2, *b3, *b4, *bc0, *bc1, *bc2, *bn0, *bn1, *bn2;
  const float *Wc2, *Wn2;
  const int* t;
  float* out;
};

struct Ctx {
  char* smem;
  uint32_t wring32, feat32, full32, empty32;
  int tid, wm, wn, lrow, lk, grp, qp, lane;
};

DEV void gen_feat(const Ctx& cx, int c, float tot) {
  const float* sx = (const float*)(cx.smem + OFF_SX);
  const float* sB = (const float*)(cx.smem + OFF_SB);
  __half* dst = (__half*)(cx.smem + OFF_FEAT + (c & 1) * 10240);
#pragma unroll
  for (int i = 0; i < 8; i++) {
    int idx = cx.tid + i * CTH;  // 128*32
    int m = idx >> 5, kk = idx & 31, kg = c * KC + kk;
    float v = 0.0f;
    if (kg < 3) {
      v = sx[m * 4 + kg];
    } else if (kg < 515) {
      int j = (kg < 259) ? (kg - 3) : (kg - 259);
      float px = sx[m * 4] * sB[j];
      px = fmaf(sx[m * 4 + 1], sB[256 + j], px);
      px = fmaf(sx[m * 4 + 2], sB[512 + j], px);
      float sv, cv;
      fsincos(px * TWO_PI, sv, cv);
      float a = fminf(fmaxf(tot - (float)j, 0.0f), 1.0f);
      v = ((kg < 259) ? sv : cv) * a;
    }
    dst[m * WS + kk] = __float2half(v);
  }
}

DEV void chunk_mma(const Ctx& cx, uint32_t aBase, int ast, int kb, uint32_t wslot,
                   float acc[2][8][4]) {
  const uint32_t aA0 = aBase + ((cx.wm * 32 + cx.lrow) * ast + kb + cx.lk) * 2;
  const uint32_t bA0 = wslot + ((cx.wn * 64 + cx.lrow) * WS + cx.lk) * 2;
#pragma unroll
  for (int ks = 0; ks < KC; ks += 16) {
    uint32_t a0[4], a1[4];
    ldsm4(a0, aA0 + ks * 2);
    ldsm4(a1, aA0 + ks * 2 + 16 * ast * 2);
#pragma unroll
    for (int np = 0; np < 4; np++) {
      uint32_t bb[4];
      ldsm4(bb, bA0 + ks * 2 + np * (16 * WS * 2));
      mma16816(acc[0][2 * np],     a0, bb[0], bb[2]);
      mma16816(acc[0][2 * np + 1], a0, bb[1], bb[3]);
      mma16816(acc[1][2 * np],     a1, bb[0], bb[2]);
      mma16816(acc[1][2 * np + 1], a1, bb[1], bb[3]);
    }
  }
}

// MODE 0: act -> sOut. MODE 1: dot Wc2 -> outac. MODE 2: dot Wn2 -> outac.
template <int MODE>
__device__ __noinline__ void layerSq(const Ctx& cx, int base, const float* sbias,
                                     const __half* sIn, __half* sOut) {
  float* outac = (float*)(cx.smem + OFF_OUTAC);
  const uint32_t in32 = smem_u32(sIn);

  float acc[2][8][4];
#pragma unroll
  for (int a = 0; a < 2; a++)
#pragma unroll
    for (int b = 0; b < 8; b++)
#pragma unroll
      for (int d = 0; d < 4; d++) acc[a][b][d] = 0.0f;

  for (int c = 0; c < 8; c++) {
    const int g = base + c;
    const int s = g % 3;
    MBAR_WAIT(cx.full32 + s * 8, (g / 3) & 1);
    chunk_mma(cx, in32, AS, c * KC, cx.wring32 + s * CH_B, acc);
    if (cx.lane == 0) MBAR_ARRIVE(cx.empty32 + s * 8);
  }

  if (MODE == 0) {
#pragma unroll
    for (int mt = 0; mt < 2; mt++) {
      const int r0 = cx.wm * 32 + mt * 16 + cx.grp;
#pragma unroll
      for (int nt = 0; nt < 8; nt++) {
        const int col = cx.wn * 64 + nt * 8 + cx.qp * 2;
        float bx = sbias[col], by = sbias[col + 1];
        *(uint32_t*)(sOut + r0 * AS + col) =
            pack2(frelu(acc[mt][nt][0] + bx), frelu(acc[mt][nt][1] + by));
        *(uint32_t*)(sOut + (r0 + 8) * AS + col) =
            pack2(frelu(acc[mt][nt][2] + bx), frelu(acc[mt][nt][3] + by));
      }
    }
  } else {
    const float* sWc2 = (const float*)(cx.smem + OFF_WC2);
    const float* sWn2 = (const float*)(cx.smem + OFF_WN2);
    constexpr int NJ = (MODE == 1) ? 3 : 1;
    float part[2][2][NJ];
#pragma unroll
    for (int a = 0; a < 2; a++)
#pragma unroll
      for (int b = 0; b < 2; b++)
#pragma unroll
        for (int j = 0; j < NJ; j++) part[a][b][j] = 0.0f;
#pragma unroll
    for (int mt = 0; mt < 2; mt++)
#pragma unroll
      for (int nt = 0; nt < 8; nt++) {
        const int col = cx.wn * 64 + nt * 8 + cx.qp * 2;
        float bx = sbias[col], by = sbias[col + 1];
        float v0 = frelu(acc[mt][nt][0] + bx), v1 = frelu(acc[mt][nt][1] + by);
        float v2 = frelu(acc[mt][nt][2] + bx), v3 = frelu(acc[mt][nt][3] + by);
#pragma unroll
        for (int j = 0; j < NJ; j++) {
          float w0 = (MODE == 1) ? sWc2[col * 3 + j] : sWn2[col];
          float w1 = (MODE == 1) ? sWc2[(col + 1) * 3 + j] : sWn2[col + 1];
          part[mt][0][j] += v0 * w0 + v1 * w1;
          part[mt][1][j] += v2 * w0 + v3 * w1;
        }
      }
#pragma unroll
    for (int mt = 0; mt < 2; mt++)
#pragma unroll
      for (int rh = 0; rh < 2; rh++)
#pragma unroll
        for (int j = 0; j < NJ; j++) {
          float v = part[mt][rh][j];
          v += __shfl_xor_sync(0xffffffffu, v, 1);
          v += __shfl_xor_sync(0xffffffffu, v, 2);
          if (cx.qp == 0)
            atomicAdd(&outac[(cx.wm * 32 + mt * 16 + rh * 8 + cx.grp) * 4 + j], v);
        }
  }
  barsync();  // layer boundary: act handoff / outac visibility
}

__global__ void __launch_bounds__(THREADS, 1) fused_mlp(Params p) {
  extern __shared__ char smem[];
  Ctx cx;
  cx.smem = smem;
  cx.tid = threadIdx.x;
  cx.lane = cx.tid & 31;
  const int wid = cx.tid >> 5;
  cx.wm = (wid >> 2) & 3; cx.wn = wid & 3;
  cx.lrow = cx.lane & 15; cx.lk = (cx.lane >> 4) << 3;
  cx.grp = cx.lane >> 2; cx.qp = cx.lane & 3;
  cx.wring32 = smem_u32(smem + OFF_WRING);
  cx.feat32 = smem_u32(smem + OFF_FEAT);
  cx.full32 = smem_u32(smem + OFF_FULL);
  cx.empty32 = smem_u32(smem + OFF_EMPTY);

  const int m0 = blockIdx.x * MT;
  float* sx = (float*)(smem + OFF_SX);
  float* sB = (float*)(smem + OFF_SB);
  float* sb0 = (float*)(smem + OFF_BIAS);
  float* sb1 = (float*)(smem + OFF_BIAS + 1024);
  float* outac = (float*)(smem + OFF_OUTAC);
  __half* actA = (__half*)(smem + OFF_ACTA);
  __half* actB = (__half*)(smem + OFF_ACTB);

  if (cx.tid == 0) {
#pragma unroll
    for (int s = 0; s < 3; s++) {
      MBAR_INIT(cx.full32 + s * 8, 1);
      MBAR_INIT(cx.empty32 + s * 8, 16);
    }
  }
  if (cx.tid < 384) {
    int m = cx.tid / 3, d = cx.tid - m * 3;
    sx[m * 4 + d] = p.x[(m0 + m) * 3 + d];
  }
  for (int i = cx.tid; i < 768; i += THREADS) sB[i] = p.B[i];
  if (cx.tid < 256) { sb0[cx.tid] = p.b0[cx.tid]; sb1[cx.tid] = p.b1[cx.tid]; }
  if (cx.tid < CTH) outac[cx.tid] = 0.0f;
  __syncthreads();  // all 544 threads; LAST full-block barrier

  if (wid == 16) {  // ---- producer warp ----
    if (cx.lane == 0) {
      for (int i = 0; i < N_CHUNKS; i++) {
        int s = i % 3;
        MBAR_WAIT(cx.empty32 + s * 8, 1 ^ ((i / 3) & 1));  // first waits pass
        issue_chunk(cx.wring32 + s * CH_B, g_Wt + (size_t)i * CH_H, cx.full32 + s * 8);
      }
    }
    return;
  }

  // ---- consumer (16 compute warps) ----
  int tbits = *p.t;
  float tval = (tbits >= 0 && tbits < (1 << 20)) ? (float)tbits : __int_as_float(tbits);
  const float tot = tval * (6000.0f / 512.0f);  // t / TAU

  // Layer 0: 17 chunks, on-the-fly features (double-buffered; per-chunk named barrier)
  {
    float acc[2][8][4];
#pragma unroll
    for (int a = 0; a < 2; a++)
#pragma unroll
      for (int b = 0; b < 8; b++)
#pragma unroll
        for (int d = 0; d < 4; d++) acc[a][b][d] = 0.0f;
    gen_feat(cx, 0, tot);
    for (int c = 0; c < L0_CHUNKS; c++) {
      barsync();  // feat buffer handoff (covers gen_feat(0) too)
      const int s = c % 3;
      MBAR_WAIT(cx.full32 + s * 8, (c / 3) & 1);
      chunk_mma(cx, cx.feat32 + (c & 1) * 10240, WS, 0, cx.wring32 + s * CH_B, acc);
      if (cx.lane == 0) MBAR_ARRIVE(cx.empty32 + s * 8);
      if (c + 1 < L0_CHUNKS) gen_feat(cx, c + 1, tot);
    }
    // epilogue -> actA (bias b0 in sb0)
#pragma unroll
    for (int mt = 0; mt < 2; mt++) {
      const int r0 = cx.wm * 32 + mt * 16 + cx.grp;
#pragma unroll
      for (int nt = 0; nt < 8; nt++) {
        const int col = cx.wn * 64 + nt * 8 + cx.qp * 2;
        float bx = sb0[col], by = sb0[col + 1];
        *(uint32_t*)(actA + r0 * AS + col) =
            pack2(frelu(acc[mt][nt][0] + bx), frelu(acc[mt][nt][1] + by));
        *(uint32_t*)(actA + (r0 + 8) * AS + col) =
            pack2(frelu(acc[mt][nt][2] + bx), frelu(acc[mt][nt][3] + by));
      }
    }
    barsync();
  }

  // overlay head-final weights (sx/sB/feat dead) + stage bias pipeline
  {
    float* sWc2 = (float*)(smem + OFF_WC2);
    float* sWn2 = (float*)(smem + OFF_WN2);
    for (int i = cx.tid; i < 768; i += CTH) sWc2[i] = p.Wc2[i];
    if (cx.tid < 256) sWn2[cx.tid] = p.Wn2[cx.tid];
  }

  if (cx.tid < 256) sb0[cx.tid] = p.b2[cx.tid];
  layerSq<0>(cx, 17, sb1, actA, actB);   // l1 (b1)
  if (cx.tid < 256) sb1[cx.tid] = p.b3[cx.tid];
  layerSq<0>(cx, 25, sb0, actB, actA);   // l2 (b2)
  if (cx.tid < 256) sb0[cx.tid] = p.b4[cx.tid];
  layerSq<0>(cx, 33, sb1, actA, actB);   // l3 (b3)
  if (cx.tid < 256) sb1[cx.tid] = p.bc0[cx.tid];
  layerSq<0>(cx, 41, sb0, actB, actA);   // l4 (b4) -> h in actA
  if (cx.tid < 256) sb0[cx.tid] = p.bc1[cx.tid];
  layerSq<0>(cx, 49, sb1, actA, actB);   // l5 (bc0)
  if (cx.tid < 256) sb1[cx.tid] = p.bn0[cx.tid];
  layerSq<1>(cx, 57, sb0, actB, nullptr);  // l6 (bc1), color dot
  if (cx.tid < 384) {
    int m = cx.tid / 3, j = cx.tid - m * 3;
    float v = outac[m * 4 + j];
    outac[m * 4 + j] = 0.0f;  // read-side zero for displacement head
    p.out[(m0 + m) * 3 + j] = tanhf(v + p.bc2[j]) * 0.5f;
  }
  if (cx.tid < 256) sb0[cx.tid] = p.bn1[cx.tid];
  layerSq<0>(cx, 65, sb1, actA, actB);   // l7 (bn0), h intact in actA
  layerSq<2>(cx, 73, sb0, actB, nullptr);  // l8 (bn1), displacement dot
  if (cx.tid < 128)
    p.out[3 * NPTS + m0 + cx.tid] = tanhf(outac[cx.tid * 4] + p.bn2[0]) * 0.1f;
}

extern "C" void kernel_launch(void* const* d_in, const int* in_sizes, int n_in,
                              void* d_out, int out_size) {
  int i = 0;
  const float* x = (const float*)d_in[i++];
  const float* B = (const float*)d_in[i++];
  const void* tp = nullptr;
  if (in_sizes[2] == 1) tp = d_in[i++];  // dict order: t at index 2
  const float *W[11], *bias[11];
  for (int j = 0; j < 11; j++) {
    W[j] = (const float*)d_in[i++];
    bias[j] = (const float*)d_in[i++];
  }
  if (!tp && i < n_in) tp = d_in[i++];

  cudaFuncSetAttribute(fused_mlp, cudaFuncAttributeMaxDynamicSharedMemorySize, SMEM_BYTES);

  constexpr int TOTAL = N_CHUNKS * CH_H;
  prep_weights<<<(TOTAL + 255) / 256, 256>>>(W[0], W[1], W[2], W[3], W[4],
                                             W[5], W[6], W[8], W[9]);

  Params p;
  p.x = x; p.B = B;
  p.b0 = bias[0]; p.b1 = bias[1]; p.b2 = bias[2]; p.b3 = bias[3]; p.b4 = bias[4];
  p.bc0 = bias[5]; p.bc1 = bias[6]; p.bc2 = bias[7];
  p.bn0 = bias[8]; p.bn1 = bias[9]; p.bn2 = bias[10];
  p.Wc2 = W[7]; p.Wn2 = W[10];
  p.t = (const int*)tp;
  p.out = (float*)d_out;

  fused_mlp<<<NPTS / MT, THREADS, SMEM_BYTES>>>(p);
}